// round 10
// baseline (speedup 1.0000x reference)
#include <cuda_runtime.h>
#include <cuda_fp16.h>
#include <math.h>
#include <stdint.h>

#define M_ROWS 4096
#define HID    768
#define NANG   20
#define QDIM   1024
#define VOCAB  30522
#define VPAD   30592        // VOCAB rounded up to multiple of 128

// Scratch (no allocations allowed)
__device__ float  g_ang[M_ROWS * NANG];
__device__ __half g_probs16[M_ROWS * QDIM];          // 8 MB
__device__ __half g_wt[(size_t)VPAD * QDIM];         // 62.7 MB, [n][k] f16
__device__ __half g_x16[M_ROWS * HID];               // 6.3 MB
__device__ __half g_wt1[HID * HID];                  // 1.2 MB, [n][k] f16
__device__ __half g_h16[M_ROWS * HID];               // 6.3 MB

// ---------------------------------------------------------------------------
// helpers
// ---------------------------------------------------------------------------
__device__ __forceinline__ uint32_t smem_u32(const void* p) {
    uint32_t a;
    asm("{ .reg .u64 t; cvta.to.shared.u64 t, %1; cvt.u32.u64 %0, t; }"
        : "=r"(a) : "l"(p));
    return a;
}
__device__ __forceinline__ void cp16(uint32_t saddr, const void* gptr) {
    asm volatile("cp.async.cg.shared.global [%0], [%1], 16;"
                 :: "r"(saddr), "l"(gptr));
}
// swizzled byte offset within a tile for (row r, 16B-chunk kc), rows folded 2/line
__device__ __forceinline__ uint32_t swz(int r, int kc) {
    const int line = r >> 1;
    const int c    = ((r & 1) << 2) + kc;
    return (uint32_t)(line * 128 + ((c ^ (line & 7)) << 4));
}

// ---------------------------------------------------------------------------
// kCvtX: x f32 -> f16
// ---------------------------------------------------------------------------
__global__ __launch_bounds__(256)
void kCvtX(const float* __restrict__ x) {
    const int i = (blockIdx.x * 256 + threadIdx.x) * 4;
    const float4 v = *(const float4*)(x + i);
    __half2* o = (__half2*)(g_x16 + i);
    o[0] = __floats2half2_rn(v.x, v.y);
    o[1] = __floats2half2_rn(v.z, v.w);
}

// ---------------------------------------------------------------------------
// kT1: dense_w f32 [k][n] -> g_wt1 f16 [n][k]  (768x768)
// ---------------------------------------------------------------------------
__global__ __launch_bounds__(256)
void kT1_transpose(const float* __restrict__ W) {
    __shared__ float t[32][33];
    const int n0 = blockIdx.x * 32;
    const int k0 = blockIdx.y * 32;
    const int tx = threadIdx.x & 31;
    const int ty = threadIdx.x >> 5;
#pragma unroll
    for (int i = 0; i < 4; i++)
        t[ty + i * 8][tx] = W[(size_t)(k0 + ty + i * 8) * HID + n0 + tx];
    __syncthreads();
#pragma unroll
    for (int i = 0; i < 4; i++) {
        const int n = n0 + ty + i * 8;
        g_wt1[(size_t)n * HID + k0 + tx] = __float2half_rn(t[tx][ty + i * 8]);
    }
}

// ---------------------------------------------------------------------------
// KT: transpose + convert proj_w (f32 [k][n]) -> g_wt (f16 [n][k]), zero pad
// ---------------------------------------------------------------------------
__global__ __launch_bounds__(256)
void kT_transpose(const float* __restrict__ Wp) {
    __shared__ float t[32][33];
    const int n0 = blockIdx.x * 32;
    const int k0 = blockIdx.y * 32;
    const int tx = threadIdx.x & 31;
    const int ty = threadIdx.x >> 5;
#pragma unroll
    for (int i = 0; i < 4; i++) {
        const int k = k0 + ty + i * 8;
        const int n = n0 + tx;
        t[ty + i * 8][tx] = (n < VOCAB) ? Wp[(size_t)k * VOCAB + n] : 0.f;
    }
    __syncthreads();
#pragma unroll
    for (int i = 0; i < 4; i++) {
        const int n = n0 + ty + i * 8;
        g_wt[(size_t)n * QDIM + k0 + tx] = __float2half_rn(t[tx][ty + i * 8]);
    }
}

// ---------------------------------------------------------------------------
// K1 GEMM: g_h16 = gelu(g_x16 @ g_wt1^T + dense_b)  (f16 x f16 -> f32)
// Same skeleton as k3: CTA 128x128x32, 4-stage cp.async, ldmatrix, swizzle.
// ---------------------------------------------------------------------------
#define BK 32
#define STAGES 4
#define A_STG 8192
#define B_STG 8192
#define B_BASE (STAGES * A_STG)
#define GEMM_SMEM (STAGES * (A_STG + B_STG))   // 64 KB

__global__ __launch_bounds__(256, 2)
void k1_gemm(const float* __restrict__ bias) {
    extern __shared__ char smem[];
    const uint32_t sA = smem_u32(smem);
    const uint32_t sB = sA + B_BASE;

    const int tid  = threadIdx.x;
    const int w    = tid >> 5;
    const int lane = tid & 31;
    const int g    = lane >> 2;
    const int tig  = lane & 3;

    const int row0 = blockIdx.x * 128;
    const int col0 = blockIdx.y * 128;
    const int warp_m = (w & 1) * 64;
    const int warp_n = (w >> 1) * 32;

    const __half* Agbase = g_x16  + (size_t)row0 * HID;
    const __half* Bgbase = g_wt1  + (size_t)col0 * HID;

    const int l16 = lane & 15;
    const int khf = lane >> 4;
    const uint32_t aLM = sA + swz(warp_m + l16, khf);
    const uint32_t bLM = sB + swz(warp_n + l16, khf);

    float acc[4][4][4];
#pragma unroll
    for (int i = 0; i < 4; i++)
#pragma unroll
        for (int j = 0; j < 4; j++)
#pragma unroll
            for (int c = 0; c < 4; c++) acc[i][j][c] = 0.f;

    const int KB = HID / BK;   // 24

#pragma unroll
    for (int s = 0; s < STAGES - 1; s++) {
        const int k0 = s * BK;
#pragma unroll
        for (int j = 0; j < 2; j++) {
            const int i = tid + j * 256;
            const int r = i >> 2, kc = i & 3;
            cp16(sA + s * A_STG + swz(r, kc), Agbase + (size_t)r * HID + k0 + kc * 8);
            cp16(sB + s * B_STG + swz(r, kc), Bgbase + (size_t)r * HID + k0 + kc * 8);
        }
        asm volatile("cp.async.commit_group;");
    }

    for (int kb = 0; kb < KB; kb++) {
        asm volatile("cp.async.wait_group %0;" :: "n"(STAGES - 2));
        __syncthreads();
        {
            const int kn = kb + STAGES - 1;
            if (kn < KB) {
                const int s  = kn & (STAGES - 1);
                const int k0 = kn * BK;
#pragma unroll
                for (int j = 0; j < 2; j++) {
                    const int i = tid + j * 256;
                    const int r = i >> 2, kc = i & 3;
                    cp16(sA + s * A_STG + swz(r, kc), Agbase + (size_t)r * HID + k0 + kc * 8);
                    cp16(sB + s * B_STG + swz(r, kc), Bgbase + (size_t)r * HID + k0 + kc * 8);
                }
            }
            asm volatile("cp.async.commit_group;");
        }

        const int s = kb & (STAGES - 1);
        const uint32_t aS = aLM + s * A_STG;
        const uint32_t bS = bLM + s * B_STG;
        uint32_t af[2][4][4], bf[2][4][2];
#pragma unroll
        for (int ks = 0; ks < 2; ks++) {
            const uint32_t kx = ks * 32;
#pragma unroll
            for (int mt = 0; mt < 4; mt++)
                asm volatile(
                    "ldmatrix.sync.aligned.m8n8.x4.shared.b16 {%0,%1,%2,%3}, [%4];"
                    : "=r"(af[ks][mt][0]), "=r"(af[ks][mt][1]),
                      "=r"(af[ks][mt][2]), "=r"(af[ks][mt][3])
                    : "r"((aS + mt * 1024) ^ kx));
#pragma unroll
            for (int ntp = 0; ntp < 2; ntp++) {
                uint32_t r0, r1, r2, r3;
                asm volatile(
                    "ldmatrix.sync.aligned.m8n8.x4.shared.b16 {%0,%1,%2,%3}, [%4];"
                    : "=r"(r0), "=r"(r1), "=r"(r2), "=r"(r3)
                    : "r"((bS + ntp * 1024) ^ kx));
                bf[ks][2*ntp][0]   = r0; bf[ks][2*ntp][1]   = r2;
                bf[ks][2*ntp+1][0] = r1; bf[ks][2*ntp+1][1] = r3;
            }
        }
#pragma unroll
        for (int ks = 0; ks < 2; ks++)
#pragma unroll
            for (int mt = 0; mt < 4; mt++)
#pragma unroll
                for (int nt = 0; nt < 4; nt++)
                    asm volatile(
                        "mma.sync.aligned.m16n8k16.row.col.f32.f16.f16.f32 "
                        "{%0,%1,%2,%3}, {%4,%5,%6,%7}, {%8,%9}, {%0,%1,%2,%3};"
                        : "+f"(acc[mt][nt][0]), "+f"(acc[mt][nt][1]),
                          "+f"(acc[mt][nt][2]), "+f"(acc[mt][nt][3])
                        : "r"(af[ks][mt][0]), "r"(af[ks][mt][1]),
                          "r"(af[ks][mt][2]), "r"(af[ks][mt][3]),
                          "r"(bf[ks][nt][0]), "r"(bf[ks][nt][1]));
    }

    // epilogue: bias + gelu -> f16
#pragma unroll
    for (int mt = 0; mt < 4; mt++) {
#pragma unroll
        for (int nt = 0; nt < 4; nt++) {
            const int row = row0 + warp_m + mt * 16 + g;
            const int col = col0 + warp_n + nt * 8 + tig * 2;
            const float b0 = bias[col], b1 = bias[col + 1];
#pragma unroll
            for (int h = 0; h < 2; h++) {
                const float v0 = acc[mt][nt][2*h]   + b0;
                const float v1 = acc[mt][nt][2*h+1] + b1;
                const float g0 = v0 * 0.5f * (1.0f + erff(v0 * 0.70710678f));
                const float g1 = v1 * 0.5f * (1.0f + erff(v1 * 0.70710678f));
                *(__half2*)(g_h16 + (size_t)(row + h * 8) * HID + col) =
                    __floats2half2_rn(g0, g1);
            }
        }
    }
}

// ---------------------------------------------------------------------------
// kLN: LayerNorm rows of g_h16, then angles = sigmoid(h @ entw + entb)*2pi
// ---------------------------------------------------------------------------
__global__ __launch_bounds__(256)
void kLN(const float* __restrict__ lnw,
         const float* __restrict__ lnb,
         const float* __restrict__ entw,
         const float* __restrict__ entb) {
    __shared__ float sh[8 * HID];
    const int row0 = blockIdx.x * 8;
    const int tid  = threadIdx.x;

    for (int i = tid; i < 8 * HID; i += 256)
        sh[i] = __half2float(g_h16[(size_t)row0 * HID + i]);
    __syncthreads();

    const int w = tid >> 5, lane = tid & 31;
    {
        float s = 0.f, s2 = 0.f;
        for (int k = lane; k < HID; k += 32) {
            const float v = sh[w * HID + k];
            s += v; s2 += v * v;
        }
#pragma unroll
        for (int o = 16; o; o >>= 1) {
            s  += __shfl_xor_sync(0xffffffffu, s,  o);
            s2 += __shfl_xor_sync(0xffffffffu, s2, o);
        }
        const float mean = s * (1.0f / HID);
        const float var  = s2 * (1.0f / HID) - mean * mean;
        const float inv  = rsqrtf(var + 1e-12f);
        for (int k = lane; k < HID; k += 32) {
            const float v = (sh[w * HID + k] - mean) * inv;
            sh[w * HID + k] = lnw[k] * v + lnb[k];
        }
    }

    for (int o = 0; o < NANG; o++) {
        float a = 0.f;
        for (int k = lane; k < HID; k += 32)
            a = fmaf(sh[w * HID + k], entw[k * NANG + o], a);
#pragma unroll
        for (int off = 16; off; off >>= 1)
            a += __shfl_xor_sync(0xffffffffu, a, off);
        if (lane == 0) {
            const float z  = a + entb[o];
            const float sg = 1.0f / (1.0f + expf(-z));
            g_ang[(row0 + w) * NANG + o] = sg * 6.283185307179586f;
        }
    }
}

// ---------------------------------------------------------------------------
// K2: quantum circuit. One block per row, 512 threads, statevector in shared.
// ---------------------------------------------------------------------------
__global__ __launch_bounds__(512)
void k2_quantum() {
    __shared__ float2 st[QDIM];
    __shared__ float cb[NANG], sb[NANG];
    const int row = blockIdx.x;
    const int tid = threadIdx.x;

    if (tid < NANG) {
        const float th = g_ang[row * NANG + tid] * 0.5f;
        sincosf(th, &sb[tid], &cb[tid]);
    }
    st[tid]       = (tid == 0) ? make_float2(1.f, 0.f) : make_float2(0.f, 0.f);
    st[tid + 512] = make_float2(0.f, 0.f);
    __syncthreads();

    for (int l = 0; l < 2; l++) {
#pragma unroll
        for (int q = 0; q < 10; q++) {
            const int b = 9 - q;
            const int S = 1 << b;
            const float c = cb[l * 10 + q];
            const float s = sb[l * 10 + q];
            const int low = tid & (S - 1);
            const int i0  = ((tid >> b) << (b + 1)) | low;
            const int i1  = i0 | S;
            const float2 a0 = st[i0];
            const float2 a1 = st[i1];
            float2 b0, b1;
            b0.x = c * a0.x + s * a1.y;
            b0.y = c * a0.y - s * a1.x;
            b1.x = c * a1.x + s * a0.y;
            b1.y = c * a1.y - s * a0.x;
            st[i0] = b0;
            st[i1] = b1;
            __syncthreads();
        }
        int j0 = tid, j1 = tid + 512;
#pragma unroll
        for (int q = 9; q >= 0; q--) {
            const int cbit = 9 - q;
            const int tbit = 9 - ((q + 1) % 10);
            j0 ^= ((j0 >> cbit) & 1) << tbit;
            j1 ^= ((j1 >> cbit) & 1) << tbit;
        }
        const float2 r0 = st[j0];
        const float2 r1 = st[j1];
        __syncthreads();
        st[tid]       = r0;
        st[tid + 512] = r1;
        __syncthreads();
    }

    const float2 v0 = st[tid];
    const float2 v1 = st[tid + 512];
    g_probs16[row * QDIM + tid]       = __float2half_rn(v0.x * v0.x + v0.y * v0.y);
    g_probs16[row * QDIM + tid + 512] = __float2half_rn(v1.x * v1.x + v1.y * v1.y);
}

// ---------------------------------------------------------------------------
// K3 v4: out = probs(4096x1024) @ g_wt^T + proj_b   (f16 x f16 -> f32)
// CTA 128x128x32, 2 CTAs/SM; 4-stage cp.async; all 12 ldmatrix hoisted
// before the 32 HMMAs of each kb.
// ---------------------------------------------------------------------------
__global__ __launch_bounds__(256, 2)
void k3_proj_f16v4(const float* __restrict__ pb,
                   float* __restrict__ out) {
    extern __shared__ char smem[];
    const uint32_t sA = smem_u32(smem);
    const uint32_t sB = sA + B_BASE;

    const int tid  = threadIdx.x;
    const int w    = tid >> 5;
    const int lane = tid & 31;
    const int g    = lane >> 2;
    const int tig  = lane & 3;

    const int row0 = blockIdx.x * 128;
    const int col0 = blockIdx.y * 128;
    const int warp_m = (w & 1) * 64;
    const int warp_n = (w >> 1) * 32;

    const __half* Agbase = g_probs16 + (size_t)row0 * QDIM;
    const __half* Bgbase = g_wt      + (size_t)col0 * QDIM;

    const int l16 = lane & 15;
    const int khf = lane >> 4;
    const uint32_t aLM = sA + swz(warp_m + l16, khf);
    const uint32_t bLM = sB + swz(warp_n + l16, khf);

    float acc[4][4][4];
#pragma unroll
    for (int i = 0; i < 4; i++)
#pragma unroll
        for (int j = 0; j < 4; j++)
#pragma unroll
            for (int c = 0; c < 4; c++) acc[i][j][c] = 0.f;

    const int KB = QDIM / BK;   // 32

#pragma unroll
    for (int s = 0; s < STAGES - 1; s++) {
        const int k0 = s * BK;
#pragma unroll
        for (int j = 0; j < 2; j++) {
            const int i = tid + j * 256;
            const int r = i >> 2, kc = i & 3;
            cp16(sA + s * A_STG + swz(r, kc), Agbase + (size_t)r * QDIM + k0 + kc * 8);
            cp16(sB + s * B_STG + swz(r, kc), Bgbase + (size_t)r * QDIM + k0 + kc * 8);
        }
        asm volatile("cp.async.commit_group;");
    }

    for (int kb = 0; kb < KB; kb++) {
        asm volatile("cp.async.wait_group %0;" :: "n"(STAGES - 2));
        __syncthreads();
        {
            const int kn = kb + STAGES - 1;
            if (kn < KB) {
                const int s  = kn & (STAGES - 1);
                const int k0 = kn * BK;
#pragma unroll
                for (int j = 0; j < 2; j++) {
                    const int i = tid + j * 256;
                    const int r = i >> 2, kc = i & 3;
                    cp16(sA + s * A_STG + swz(r, kc), Agbase + (size_t)r * QDIM + k0 + kc * 8);
                    cp16(sB + s * B_STG + swz(r, kc), Bgbase + (size_t)r * QDIM + k0 + kc * 8);
                }
            }
            asm volatile("cp.async.commit_group;");
        }

        const int s = kb & (STAGES - 1);
        const uint32_t aS = aLM + s * A_STG;
        const uint32_t bS = bLM + s * B_STG;
        uint32_t af[2][4][4], bf[2][4][2];
#pragma unroll
        for (int ks = 0; ks < 2; ks++) {
            const uint32_t kx = ks * 32;
#pragma unroll
            for (int mt = 0; mt < 4; mt++)
                asm volatile(
                    "ldmatrix.sync.aligned.m8n8.x4.shared.b16 {%0,%1,%2,%3}, [%4];"
                    : "=r"(af[ks][mt][0]), "=r"(af[ks][mt][1]),
                      "=r"(af[ks][mt][2]), "=r"(af[ks][mt][3])
                    : "r"((aS + mt * 1024) ^ kx));
#pragma unroll
            for (int ntp = 0; ntp < 2; ntp++) {
                uint32_t r0, r1, r2, r3;
                asm volatile(
                    "ldmatrix.sync.aligned.m8n8.x4.shared.b16 {%0,%1,%2,%3}, [%4];"
                    : "=r"(r0), "=r"(r1), "=r"(r2), "=r"(r3)
                    : "r"((bS + ntp * 1024) ^ kx));
                bf[ks][2*ntp][0]   = r0; bf[ks][2*ntp][1]   = r2;
                bf[ks][2*ntp+1][0] = r1; bf[ks][2*ntp+1][1] = r3;
            }
        }
#pragma unroll
        for (int ks = 0; ks < 2; ks++)
#pragma unroll
            for (int mt = 0; mt < 4; mt++)
#pragma unroll
                for (int nt = 0; nt < 4; nt++)
                    asm volatile(
                        "mma.sync.aligned.m16n8k16.row.col.f32.f16.f16.f32 "
                        "{%0,%1,%2,%3}, {%4,%5,%6,%7}, {%8,%9}, {%0,%1,%2,%3};"
                        : "+f"(acc[mt][nt][0]), "+f"(acc[mt][nt][1]),
                          "+f"(acc[mt][nt][2]), "+f"(acc[mt][nt][3])
                        : "r"(af[ks][mt][0]), "r"(af[ks][mt][1]),
                          "r"(af[ks][mt][2]), "r"(af[ks][mt][3]),
                          "r"(bf[ks][nt][0]), "r"(bf[ks][nt][1]));
    }

    // epilogue
#pragma unroll
    for (int mt = 0; mt < 4; mt++) {
#pragma unroll
        for (int nt = 0; nt < 4; nt++) {
            const int row = row0 + warp_m + mt * 16 + g;
            const int col = col0 + warp_n + nt * 8 + tig * 2;
            if (col < VOCAB) {
                const float b0 = pb[col], b1 = pb[col + 1];
                float2 v0 = make_float2(acc[mt][nt][0] + b0, acc[mt][nt][1] + b1);
                float2 v1 = make_float2(acc[mt][nt][2] + b0, acc[mt][nt][3] + b1);
                __stcs((float2*)(out + (size_t)row * VOCAB + col), v0);
                __stcs((float2*)(out + (size_t)(row + 8) * VOCAB + col), v1);
            }
        }
    }
}

// ---------------------------------------------------------------------------
extern "C" void kernel_launch(void* const* d_in, const int* in_sizes, int n_in,
                              void* d_out, int out_size) {
    const float* x    = (const float*)d_in[0];
    const float* W    = (const float*)d_in[1];
    const float* db   = (const float*)d_in[2];
    const float* lnw  = (const float*)d_in[3];
    const float* lnb  = (const float*)d_in[4];
    const float* entw = (const float*)d_in[5];
    const float* entb = (const float*)d_in[6];
    const float* pw   = (const float*)d_in[7];
    const float* pb   = (const float*)d_in[8];
    float* out = (float*)d_out;

    kCvtX<<<M_ROWS * HID / 1024, 256>>>(x);
    dim3 gT1(HID / 32, HID / 32);
    kT1_transpose<<<gT1, 256>>>(W);
    dim3 gT(VPAD / 32, QDIM / 32);
    kT_transpose<<<gT, 256>>>(pw);

    cudaFuncSetAttribute(k1_gemm,
                         cudaFuncAttributeMaxDynamicSharedMemorySize, GEMM_SMEM);
    dim3 g1(M_ROWS / 128, HID / 128);      // (32, 6)
    k1_gemm<<<g1, 256, GEMM_SMEM>>>(db);

    kLN<<<M_ROWS / 8, 256>>>(lnw, lnb, entw, entb);
    k2_quantum<<<M_ROWS, 512>>>();

    cudaFuncSetAttribute(k3_proj_f16v4,
                         cudaFuncAttributeMaxDynamicSharedMemorySize, GEMM_SMEM);
    dim3 g3(M_ROWS / 128, VPAD / 128);     // (32, 239)
    k3_proj_f16v4<<<g3, 256, GEMM_SMEM>>>(pb, out);
}

// round 11
// speedup vs baseline: 1.5086x; 1.5086x over previous
#include <cuda_runtime.h>
#include <cuda_fp16.h>
#include <math.h>
#include <stdint.h>

#define M_ROWS 4096
#define HID    768
#define NANG   20
#define QDIM   1024
#define VOCAB  30522
#define VPAD   30592        // VOCAB rounded up to multiple of 128

// Scratch (no allocations allowed)
__device__ float  g_ang[M_ROWS * NANG];
__device__ __half g_probs16[M_ROWS * QDIM];          // 8 MB
__device__ __half g_wt[(size_t)VPAD * QDIM];         // 62.7 MB, [n][k] f16
__device__ __half g_x16[M_ROWS * HID];               // 6.3 MB
__device__ __half g_wt1[HID * HID];                  // 1.2 MB, [n][k] f16
__device__ __half g_h16[M_ROWS * HID];               // 6.3 MB

// ---------------------------------------------------------------------------
// helpers
// ---------------------------------------------------------------------------
__device__ __forceinline__ uint32_t smem_u32(const void* p) {
    uint32_t a;
    asm("{ .reg .u64 t; cvta.to.shared.u64 t, %1; cvt.u32.u64 %0, t; }"
        : "=r"(a) : "l"(p));
    return a;
}
__device__ __forceinline__ void cp16(uint32_t saddr, const void* gptr) {
    asm volatile("cp.async.cg.shared.global [%0], [%1], 16;"
                 :: "r"(saddr), "l"(gptr));
}
// swizzled byte offset within a tile for (row r, 16B-chunk kc), rows folded 2/line
__device__ __forceinline__ uint32_t swz(int r, int kc) {
    const int line = r >> 1;
    const int c    = ((r & 1) << 2) + kc;
    return (uint32_t)(line * 128 + ((c ^ (line & 7)) << 4));
}

// ---------------------------------------------------------------------------
// kCvtX: x f32 -> f16
// ---------------------------------------------------------------------------
__global__ __launch_bounds__(256)
void kCvtX(const float* __restrict__ x) {
    const int i = (blockIdx.x * 256 + threadIdx.x) * 4;
    const float4 v = *(const float4*)(x + i);
    __half2* o = (__half2*)(g_x16 + i);
    o[0] = __floats2half2_rn(v.x, v.y);
    o[1] = __floats2half2_rn(v.z, v.w);
}

// ---------------------------------------------------------------------------
// kT1: dense_w f32 [k][n] -> g_wt1 f16 [n][k]  (768x768)
// ---------------------------------------------------------------------------
__global__ __launch_bounds__(256)
void kT1_transpose(const float* __restrict__ W) {
    __shared__ float t[32][33];
    const int n0 = blockIdx.x * 32;
    const int k0 = blockIdx.y * 32;
    const int tx = threadIdx.x & 31;
    const int ty = threadIdx.x >> 5;
#pragma unroll
    for (int i = 0; i < 4; i++)
        t[ty + i * 8][tx] = W[(size_t)(k0 + ty + i * 8) * HID + n0 + tx];
    __syncthreads();
#pragma unroll
    for (int i = 0; i < 4; i++) {
        const int n = n0 + ty + i * 8;
        g_wt1[(size_t)n * HID + k0 + tx] = __float2half_rn(t[tx][ty + i * 8]);
    }
}

// ---------------------------------------------------------------------------
// KT: transpose + convert proj_w (f32 [k][n]) -> g_wt (f16 [n][k]), zero pad
// ---------------------------------------------------------------------------
__global__ __launch_bounds__(256)
void kT_transpose(const float* __restrict__ Wp) {
    __shared__ float t[32][33];
    const int n0 = blockIdx.x * 32;
    const int k0 = blockIdx.y * 32;
    const int tx = threadIdx.x & 31;
    const int ty = threadIdx.x >> 5;
#pragma unroll
    for (int i = 0; i < 4; i++) {
        const int k = k0 + ty + i * 8;
        const int n = n0 + tx;
        t[ty + i * 8][tx] = (n < VOCAB) ? Wp[(size_t)k * VOCAB + n] : 0.f;
    }
    __syncthreads();
#pragma unroll
    for (int i = 0; i < 4; i++) {
        const int n = n0 + ty + i * 8;
        g_wt[(size_t)n * QDIM + k0 + tx] = __float2half_rn(t[tx][ty + i * 8]);
    }
}

// ---------------------------------------------------------------------------
// K1 GEMM: g_h16 = gelu(g_x16 @ g_wt1^T + dense_b)  (f16 x f16 -> f32)
// CTA 128x128x32, 4-stage cp.async, ldmatrix, swizzle. (measured 49us)
// ---------------------------------------------------------------------------
#define BK 32
#define STAGES 4
#define A_STG 8192
#define B_STG 8192
#define B_BASE (STAGES * A_STG)
#define GEMM_SMEM (STAGES * (A_STG + B_STG))   // 64 KB

__global__ __launch_bounds__(256, 2)
void k1_gemm(const float* __restrict__ bias) {
    extern __shared__ char smem[];
    const uint32_t sA = smem_u32(smem);
    const uint32_t sB = sA + B_BASE;

    const int tid  = threadIdx.x;
    const int w    = tid >> 5;
    const int lane = tid & 31;
    const int g    = lane >> 2;
    const int tig  = lane & 3;

    const int row0 = blockIdx.x * 128;
    const int col0 = blockIdx.y * 128;
    const int warp_m = (w & 1) * 64;
    const int warp_n = (w >> 1) * 32;

    const __half* Agbase = g_x16  + (size_t)row0 * HID;
    const __half* Bgbase = g_wt1  + (size_t)col0 * HID;

    const int l16 = lane & 15;
    const int khf = lane >> 4;
    const uint32_t aLM = sA + swz(warp_m + l16, khf);
    const uint32_t bLM = sB + swz(warp_n + l16, khf);

    float acc[4][4][4];
#pragma unroll
    for (int i = 0; i < 4; i++)
#pragma unroll
        for (int j = 0; j < 4; j++)
#pragma unroll
            for (int c = 0; c < 4; c++) acc[i][j][c] = 0.f;

    const int KB = HID / BK;   // 24

#pragma unroll
    for (int s = 0; s < STAGES - 1; s++) {
        const int k0 = s * BK;
#pragma unroll
        for (int j = 0; j < 2; j++) {
            const int i = tid + j * 256;
            const int r = i >> 2, kc = i & 3;
            cp16(sA + s * A_STG + swz(r, kc), Agbase + (size_t)r * HID + k0 + kc * 8);
            cp16(sB + s * B_STG + swz(r, kc), Bgbase + (size_t)r * HID + k0 + kc * 8);
        }
        asm volatile("cp.async.commit_group;");
    }

    for (int kb = 0; kb < KB; kb++) {
        asm volatile("cp.async.wait_group %0;" :: "n"(STAGES - 2));
        __syncthreads();
        {
            const int kn = kb + STAGES - 1;
            if (kn < KB) {
                const int s  = kn & (STAGES - 1);
                const int k0 = kn * BK;
#pragma unroll
                for (int j = 0; j < 2; j++) {
                    const int i = tid + j * 256;
                    const int r = i >> 2, kc = i & 3;
                    cp16(sA + s * A_STG + swz(r, kc), Agbase + (size_t)r * HID + k0 + kc * 8);
                    cp16(sB + s * B_STG + swz(r, kc), Bgbase + (size_t)r * HID + k0 + kc * 8);
                }
            }
            asm volatile("cp.async.commit_group;");
        }

        const int s = kb & (STAGES - 1);
        const uint32_t aS = aLM + s * A_STG;
        const uint32_t bS = bLM + s * B_STG;
#pragma unroll
        for (int ks = 0; ks < 2; ks++) {
            const uint32_t kx = ks * 32;
            uint32_t af[4][4];
#pragma unroll
            for (int mt = 0; mt < 4; mt++)
                asm volatile(
                    "ldmatrix.sync.aligned.m8n8.x4.shared.b16 {%0,%1,%2,%3}, [%4];"
                    : "=r"(af[mt][0]), "=r"(af[mt][1]),
                      "=r"(af[mt][2]), "=r"(af[mt][3])
                    : "r"((aS + mt * 1024) ^ kx));
            uint32_t bf[4][2];
#pragma unroll
            for (int ntp = 0; ntp < 2; ntp++) {
                uint32_t r0, r1, r2, r3;
                asm volatile(
                    "ldmatrix.sync.aligned.m8n8.x4.shared.b16 {%0,%1,%2,%3}, [%4];"
                    : "=r"(r0), "=r"(r1), "=r"(r2), "=r"(r3)
                    : "r"((bS + ntp * 1024) ^ kx));
                bf[2*ntp][0]   = r0; bf[2*ntp][1]   = r2;
                bf[2*ntp+1][0] = r1; bf[2*ntp+1][1] = r3;
            }
#pragma unroll
            for (int mt = 0; mt < 4; mt++)
#pragma unroll
                for (int nt = 0; nt < 4; nt++)
                    asm volatile(
                        "mma.sync.aligned.m16n8k16.row.col.f32.f16.f16.f32 "
                        "{%0,%1,%2,%3}, {%4,%5,%6,%7}, {%8,%9}, {%0,%1,%2,%3};"
                        : "+f"(acc[mt][nt][0]), "+f"(acc[mt][nt][1]),
                          "+f"(acc[mt][nt][2]), "+f"(acc[mt][nt][3])
                        : "r"(af[mt][0]), "r"(af[mt][1]),
                          "r"(af[mt][2]), "r"(af[mt][3]),
                          "r"(bf[nt][0]), "r"(bf[nt][1]));
        }
    }

    // epilogue: bias + gelu -> f16
#pragma unroll
    for (int mt = 0; mt < 4; mt++) {
#pragma unroll
        for (int nt = 0; nt < 4; nt++) {
            const int row = row0 + warp_m + mt * 16 + g;
            const int col = col0 + warp_n + nt * 8 + tig * 2;
            const float b0 = bias[col], b1 = bias[col + 1];
#pragma unroll
            for (int h = 0; h < 2; h++) {
                const float v0 = acc[mt][nt][2*h]   + b0;
                const float v1 = acc[mt][nt][2*h+1] + b1;
                const float g0 = v0 * 0.5f * (1.0f + erff(v0 * 0.70710678f));
                const float g1 = v1 * 0.5f * (1.0f + erff(v1 * 0.70710678f));
                *(__half2*)(g_h16 + (size_t)(row + h * 8) * HID + col) =
                    __floats2half2_rn(g0, g1);
            }
        }
    }
}

// ---------------------------------------------------------------------------
// kLN: LayerNorm rows of g_h16, then angles = sigmoid(h @ entw + entb)*2pi
// ---------------------------------------------------------------------------
__global__ __launch_bounds__(256)
void kLN(const float* __restrict__ lnw,
         const float* __restrict__ lnb,
         const float* __restrict__ entw,
         const float* __restrict__ entb) {
    __shared__ float sh[8 * HID];
    const int row0 = blockIdx.x * 8;
    const int tid  = threadIdx.x;

    for (int i = tid; i < 4 * HID; i += 256) {
        const __half2 v = *((const __half2*)g_h16 + (size_t)row0 * (HID/2) + i);
        const float2 f = __half22float2(v);
        sh[2*i] = f.x; sh[2*i+1] = f.y;
    }
    __syncthreads();

    const int w = tid >> 5, lane = tid & 31;
    {
        float s = 0.f, s2 = 0.f;
        for (int k = lane; k < HID; k += 32) {
            const float v = sh[w * HID + k];
            s += v; s2 += v * v;
        }
#pragma unroll
        for (int o = 16; o; o >>= 1) {
            s  += __shfl_xor_sync(0xffffffffu, s,  o);
            s2 += __shfl_xor_sync(0xffffffffu, s2, o);
        }
        const float mean = s * (1.0f / HID);
        const float var  = s2 * (1.0f / HID) - mean * mean;
        const float inv  = rsqrtf(var + 1e-12f);
        for (int k = lane; k < HID; k += 32) {
            const float v = (sh[w * HID + k] - mean) * inv;
            sh[w * HID + k] = lnw[k] * v + lnb[k];
        }
    }

    for (int o = 0; o < NANG; o++) {
        float a = 0.f;
        for (int k = lane; k < HID; k += 32)
            a = fmaf(sh[w * HID + k], entw[k * NANG + o], a);
#pragma unroll
        for (int off = 16; off; off >>= 1)
            a += __shfl_xor_sync(0xffffffffu, a, off);
        if (lane == 0) {
            const float z  = a + entb[o];
            const float sg = 1.0f / (1.0f + expf(-z));
            g_ang[(row0 + w) * NANG + o] = sg * 6.283185307179586f;
        }
    }
}

// ---------------------------------------------------------------------------
// K2: quantum circuit. One block per row, 512 threads, statevector in shared.
// ---------------------------------------------------------------------------
__global__ __launch_bounds__(512)
void k2_quantum() {
    __shared__ float2 st[QDIM];
    __shared__ float cb[NANG], sb[NANG];
    const int row = blockIdx.x;
    const int tid = threadIdx.x;

    if (tid < NANG) {
        const float th = g_ang[row * NANG + tid] * 0.5f;
        sincosf(th, &sb[tid], &cb[tid]);
    }
    st[tid]       = (tid == 0) ? make_float2(1.f, 0.f) : make_float2(0.f, 0.f);
    st[tid + 512] = make_float2(0.f, 0.f);
    __syncthreads();

    for (int l = 0; l < 2; l++) {
#pragma unroll
        for (int q = 0; q < 10; q++) {
            const int b = 9 - q;
            const int S = 1 << b;
            const float c = cb[l * 10 + q];
            const float s = sb[l * 10 + q];
            const int low = tid & (S - 1);
            const int i0  = ((tid >> b) << (b + 1)) | low;
            const int i1  = i0 | S;
            const float2 a0 = st[i0];
            const float2 a1 = st[i1];
            float2 b0, b1;
            b0.x = c * a0.x + s * a1.y;
            b0.y = c * a0.y - s * a1.x;
            b1.x = c * a1.x + s * a0.y;
            b1.y = c * a1.y - s * a0.x;
            st[i0] = b0;
            st[i1] = b1;
            __syncthreads();
        }
        int j0 = tid, j1 = tid + 512;
#pragma unroll
        for (int q = 9; q >= 0; q--) {
            const int cbit = 9 - q;
            const int tbit = 9 - ((q + 1) % 10);
            j0 ^= ((j0 >> cbit) & 1) << tbit;
            j1 ^= ((j1 >> cbit) & 1) << tbit;
        }
        const float2 r0 = st[j0];
        const float2 r1 = st[j1];
        __syncthreads();
        st[tid]       = r0;
        st[tid + 512] = r1;
        __syncthreads();
    }

    const float2 v0 = st[tid];
    const float2 v1 = st[tid + 512];
    g_probs16[row * QDIM + tid]       = __float2half_rn(v0.x * v0.x + v0.y * v0.y);
    g_probs16[row * QDIM + tid + 512] = __float2half_rn(v1.x * v1.x + v1.y * v1.y);
}

// ---------------------------------------------------------------------------
// K3 v3 (reverted from v4): out = probs @ g_wt^T + proj_b  (f16 x f16 -> f32)
// CTA 128x128x32, 2 CTAs/SM; 4-stage cp.async; per-ks fragment loads
// (NOT hoisted — hoisting both ks groups spilled regs and doubled runtime).
// ---------------------------------------------------------------------------
__global__ __launch_bounds__(256, 2)
void k3_proj_f16v3(const float* __restrict__ pb,
                   float* __restrict__ out) {
    extern __shared__ char smem[];
    const uint32_t sA = smem_u32(smem);
    const uint32_t sB = sA + B_BASE;

    const int tid  = threadIdx.x;
    const int w    = tid >> 5;
    const int lane = tid & 31;
    const int g    = lane >> 2;
    const int tig  = lane & 3;

    const int row0 = blockIdx.x * 128;
    const int col0 = blockIdx.y * 128;
    const int warp_m = (w & 1) * 64;
    const int warp_n = (w >> 1) * 32;

    const __half* Agbase = g_probs16 + (size_t)row0 * QDIM;
    const __half* Bgbase = g_wt      + (size_t)col0 * QDIM;

    const int l16 = lane & 15;
    const int khf = lane >> 4;
    const uint32_t aLM = sA + swz(warp_m + l16, khf);
    const uint32_t bLM = sB + swz(warp_n + l16, khf);

    float acc[4][4][4];
#pragma unroll
    for (int i = 0; i < 4; i++)
#pragma unroll
        for (int j = 0; j < 4; j++)
#pragma unroll
            for (int c = 0; c < 4; c++) acc[i][j][c] = 0.f;

    const int KB = QDIM / BK;   // 32

#pragma unroll
    for (int s = 0; s < STAGES - 1; s++) {
        const int k0 = s * BK;
#pragma unroll
        for (int j = 0; j < 2; j++) {
            const int i = tid + j * 256;
            const int r = i >> 2, kc = i & 3;
            cp16(sA + s * A_STG + swz(r, kc), Agbase + (size_t)r * QDIM + k0 + kc * 8);
            cp16(sB + s * B_STG + swz(r, kc), Bgbase + (size_t)r * QDIM + k0 + kc * 8);
        }
        asm volatile("cp.async.commit_group;");
    }

    for (int kb = 0; kb < KB; kb++) {
        asm volatile("cp.async.wait_group %0;" :: "n"(STAGES - 2));
        __syncthreads();
        {
            const int kn = kb + STAGES - 1;
            if (kn < KB) {
                const int s  = kn & (STAGES - 1);
                const int k0 = kn * BK;
#pragma unroll
                for (int j = 0; j < 2; j++) {
                    const int i = tid + j * 256;
                    const int r = i >> 2, kc = i & 3;
                    cp16(sA + s * A_STG + swz(r, kc), Agbase + (size_t)r * QDIM + k0 + kc * 8);
                    cp16(sB + s * B_STG + swz(r, kc), Bgbase + (size_t)r * QDIM + k0 + kc * 8);
                }
            }
            asm volatile("cp.async.commit_group;");
        }

        const int s = kb & (STAGES - 1);
        const uint32_t aS = aLM + s * A_STG;
        const uint32_t bS = bLM + s * B_STG;
#pragma unroll
        for (int ks = 0; ks < 2; ks++) {
            const uint32_t kx = ks * 32;    // toggle chunk bit1 (16 halves)
            uint32_t af[4][4];
#pragma unroll
            for (int mt = 0; mt < 4; mt++) {
                asm volatile(
                    "ldmatrix.sync.aligned.m8n8.x4.shared.b16 {%0,%1,%2,%3}, [%4];"
                    : "=r"(af[mt][0]), "=r"(af[mt][1]),
                      "=r"(af[mt][2]), "=r"(af[mt][3])
                    : "r"((aS + mt * 1024) ^ kx));
            }
            uint32_t bf[4][2];
#pragma unroll
            for (int ntp = 0; ntp < 2; ntp++) {
                uint32_t r0, r1, r2, r3;
                asm volatile(
                    "ldmatrix.sync.aligned.m8n8.x4.shared.b16 {%0,%1,%2,%3}, [%4];"
                    : "=r"(r0), "=r"(r1), "=r"(r2), "=r"(r3)
                    : "r"((bS + ntp * 1024) ^ kx));
                bf[2*ntp][0]   = r0; bf[2*ntp][1]   = r2;
                bf[2*ntp+1][0] = r1; bf[2*ntp+1][1] = r3;
            }
#pragma unroll
            for (int mt = 0; mt < 4; mt++)
#pragma unroll
                for (int nt = 0; nt < 4; nt++) {
                    asm volatile(
                        "mma.sync.aligned.m16n8k16.row.col.f32.f16.f16.f32 "
                        "{%0,%1,%2,%3}, {%4,%5,%6,%7}, {%8,%9}, {%0,%1,%2,%3};"
                        : "+f"(acc[mt][nt][0]), "+f"(acc[mt][nt][1]),
                          "+f"(acc[mt][nt][2]), "+f"(acc[mt][nt][3])
                        : "r"(af[mt][0]), "r"(af[mt][1]),
                          "r"(af[mt][2]), "r"(af[mt][3]),
                          "r"(bf[nt][0]), "r"(bf[nt][1]));
                }
        }
    }

    // epilogue
#pragma unroll
    for (int mt = 0; mt < 4; mt++) {
#pragma unroll
        for (int nt = 0; nt < 4; nt++) {
            const int row = row0 + warp_m + mt * 16 + g;
            const int col = col0 + warp_n + nt * 8 + tig * 2;
            if (col < VOCAB) {   // VOCAB even -> pair never straddles
                const float b0 = pb[col], b1 = pb[col + 1];
                float2 v0 = make_float2(acc[mt][nt][0] + b0, acc[mt][nt][1] + b1);
                float2 v1 = make_float2(acc[mt][nt][2] + b0, acc[mt][nt][3] + b1);
                __stcs((float2*)(out + (size_t)row * VOCAB + col), v0);
                __stcs((float2*)(out + (size_t)(row + 8) * VOCAB + col), v1);
            }
        }
    }
}

// ---------------------------------------------------------------------------
extern "C" void kernel_launch(void* const* d_in, const int* in_sizes, int n_in,
                              void* d_out, int out_size) {
    const float* x    = (const float*)d_in[0];
    const float* W    = (const float*)d_in[1];
    const float* db   = (const float*)d_in[2];
    const float* lnw  = (const float*)d_in[3];
    const float* lnb  = (const float*)d_in[4];
    const float* entw = (const float*)d_in[5];
    const float* entb = (const float*)d_in[6];
    const float* pw   = (const float*)d_in[7];
    const float* pb   = (const float*)d_in[8];
    float* out = (float*)d_out;

    kCvtX<<<M_ROWS * HID / 1024, 256>>>(x);
    dim3 gT1(HID / 32, HID / 32);
    kT1_transpose<<<gT1, 256>>>(W);
    dim3 gT(VPAD / 32, QDIM / 32);
    kT_transpose<<<gT, 256>>>(pw);

    cudaFuncSetAttribute(k1_gemm,
                         cudaFuncAttributeMaxDynamicSharedMemorySize, GEMM_SMEM);
    dim3 g1(M_ROWS / 128, HID / 128);      // (32, 6)
    k1_gemm<<<g1, 256, GEMM_SMEM>>>(db);

    kLN<<<M_ROWS / 8, 256>>>(lnw, lnb, entw, entb);
    k2_quantum<<<M_ROWS, 512>>>();

    cudaFuncSetAttribute(k3_proj_f16v3,
                         cudaFuncAttributeMaxDynamicSharedMemorySize, GEMM_SMEM);
    dim3 g3(M_ROWS / 128, VPAD / 128);     // (32, 239)
    k3_proj_f16v3<<<g3, 256, GEMM_SMEM>>>(pb, out);
}

// round 13
// speedup vs baseline: 1.5485x; 1.0265x over previous
#include <cuda_runtime.h>
#include <cuda_fp16.h>
#include <math.h>
#include <stdint.h>

#define M_ROWS 4096
#define HID    768
#define NANG   20
#define QDIM   1024
#define VOCAB  30522
#define VPAD   30592        // VOCAB rounded up to multiple of 128

// Scratch (no allocations allowed)
__device__ float  g_ang[M_ROWS * NANG];
__device__ __half g_probs16[M_ROWS * QDIM];          // 8 MB
__device__ __half g_wt[(size_t)VPAD * QDIM];         // 62.7 MB, [n][k] f16
__device__ __half g_x16[M_ROWS * HID];               // 6.3 MB
__device__ __half g_wt1[HID * HID];                  // 1.2 MB, [n][k] f16
__device__ __half g_h16[M_ROWS * HID];               // 6.3 MB

// ---------------------------------------------------------------------------
// helpers
// ---------------------------------------------------------------------------
__device__ __forceinline__ uint32_t smem_u32(const void* p) {
    uint32_t a;
    asm("{ .reg .u64 t; cvta.to.shared.u64 t, %1; cvt.u32.u64 %0, t; }"
        : "=r"(a) : "l"(p));
    return a;
}
__device__ __forceinline__ void cp16(uint32_t saddr, const void* gptr) {
    asm volatile("cp.async.cg.shared.global [%0], [%1], 16;"
                 :: "r"(saddr), "l"(gptr));
}
// k1 swizzle: rows folded 2/line (64B data rows)
__device__ __forceinline__ uint32_t swz(int r, int kc) {
    const int line = r >> 1;
    const int c    = ((r & 1) << 2) + kc;
    return (uint32_t)(line * 128 + ((c ^ (line & 7)) << 4));
}
// k3 swizzle: one 128B row per line, chunk kc in 0..7
__device__ __forceinline__ uint32_t swz64(int r, int kc) {
    return (uint32_t)(r * 128 + ((kc ^ (r & 7)) << 4));
}

// ---------------------------------------------------------------------------
// kCvtX: x f32 -> f16
// ---------------------------------------------------------------------------
__global__ __launch_bounds__(256)
void kCvtX(const float* __restrict__ x) {
    const int i = (blockIdx.x * 256 + threadIdx.x) * 4;
    const float4 v = *(const float4*)(x + i);
    __half2* o = (__half2*)(g_x16 + i);
    o[0] = __floats2half2_rn(v.x, v.y);
    o[1] = __floats2half2_rn(v.z, v.w);
}

// ---------------------------------------------------------------------------
// kT1: dense_w f32 [k][n] -> g_wt1 f16 [n][k]  (768x768)
// ---------------------------------------------------------------------------
__global__ __launch_bounds__(256)
void kT1_transpose(const float* __restrict__ W) {
    __shared__ float t[32][33];
    const int n0 = blockIdx.x * 32;
    const int k0 = blockIdx.y * 32;
    const int tx = threadIdx.x & 31;
    const int ty = threadIdx.x >> 5;
#pragma unroll
    for (int i = 0; i < 4; i++)
        t[ty + i * 8][tx] = W[(size_t)(k0 + ty + i * 8) * HID + n0 + tx];
    __syncthreads();
#pragma unroll
    for (int i = 0; i < 4; i++) {
        const int n = n0 + ty + i * 8;
        g_wt1[(size_t)n * HID + k0 + tx] = __float2half_rn(t[tx][ty + i * 8]);
    }
}

// ---------------------------------------------------------------------------
// KT: transpose + convert proj_w (f32 [k][n]) -> g_wt (f16 [n][k]), zero pad
// ---------------------------------------------------------------------------
__global__ __launch_bounds__(256)
void kT_transpose(const float* __restrict__ Wp) {
    __shared__ float t[32][33];
    const int n0 = blockIdx.x * 32;
    const int k0 = blockIdx.y * 32;
    const int tx = threadIdx.x & 31;
    const int ty = threadIdx.x >> 5;
#pragma unroll
    for (int i = 0; i < 4; i++) {
        const int k = k0 + ty + i * 8;
        const int n = n0 + tx;
        t[ty + i * 8][tx] = (n < VOCAB) ? Wp[(size_t)k * VOCAB + n] : 0.f;
    }
    __syncthreads();
#pragma unroll
    for (int i = 0; i < 4; i++) {
        const int n = n0 + ty + i * 8;
        g_wt[(size_t)n * QDIM + k0 + tx] = __float2half_rn(t[tx][ty + i * 8]);
    }
}

// ---------------------------------------------------------------------------
// K1 GEMM: g_h16 = gelu(g_x16 @ g_wt1^T + dense_b)  (measured 32us — keep)
// CTA 128x128x32, 4-stage cp.async, ldmatrix, swizzle.
// ---------------------------------------------------------------------------
#define BK 32
#define STAGES 4
#define A_STG 8192
#define B_STG 8192
#define B_BASE (STAGES * A_STG)
#define GEMM_SMEM (STAGES * (A_STG + B_STG))   // 64 KB

__global__ __launch_bounds__(256, 2)
void k1_gemm(const float* __restrict__ bias) {
    extern __shared__ char smem[];
    const uint32_t sA = smem_u32(smem);
    const uint32_t sB = sA + B_BASE;

    const int tid  = threadIdx.x;
    const int w    = tid >> 5;
    const int lane = tid & 31;
    const int g    = lane >> 2;
    const int tig  = lane & 3;

    const int row0 = blockIdx.x * 128;
    const int col0 = blockIdx.y * 128;
    const int warp_m = (w & 1) * 64;
    const int warp_n = (w >> 1) * 32;

    const __half* Agbase = g_x16  + (size_t)row0 * HID;
    const __half* Bgbase = g_wt1  + (size_t)col0 * HID;

    const int l16 = lane & 15;
    const int khf = lane >> 4;
    const uint32_t aLM = sA + swz(warp_m + l16, khf);
    const uint32_t bLM = sB + swz(warp_n + l16, khf);

    float acc[4][4][4];
#pragma unroll
    for (int i = 0; i < 4; i++)
#pragma unroll
        for (int j = 0; j < 4; j++)
#pragma unroll
            for (int c = 0; c < 4; c++) acc[i][j][c] = 0.f;

    const int KB = HID / BK;   // 24

#pragma unroll
    for (int s = 0; s < STAGES - 1; s++) {
        const int k0 = s * BK;
#pragma unroll
        for (int j = 0; j < 2; j++) {
            const int i = tid + j * 256;
            const int r = i >> 2, kc = i & 3;
            cp16(sA + s * A_STG + swz(r, kc), Agbase + (size_t)r * HID + k0 + kc * 8);
            cp16(sB + s * B_STG + swz(r, kc), Bgbase + (size_t)r * HID + k0 + kc * 8);
        }
        asm volatile("cp.async.commit_group;");
    }

    for (int kb = 0; kb < KB; kb++) {
        asm volatile("cp.async.wait_group %0;" :: "n"(STAGES - 2));
        __syncthreads();
        {
            const int kn = kb + STAGES - 1;
            if (kn < KB) {
                const int s  = kn & (STAGES - 1);
                const int k0 = kn * BK;
#pragma unroll
                for (int j = 0; j < 2; j++) {
                    const int i = tid + j * 256;
                    const int r = i >> 2, kc = i & 3;
                    cp16(sA + s * A_STG + swz(r, kc), Agbase + (size_t)r * HID + k0 + kc * 8);
                    cp16(sB + s * B_STG + swz(r, kc), Bgbase + (size_t)r * HID + k0 + kc * 8);
                }
            }
            asm volatile("cp.async.commit_group;");
        }

        const int s = kb & (STAGES - 1);
        const uint32_t aS = aLM + s * A_STG;
        const uint32_t bS = bLM + s * B_STG;
#pragma unroll
        for (int ks = 0; ks < 2; ks++) {
            const uint32_t kx = ks * 32;
            uint32_t af[4][4];
#pragma unroll
            for (int mt = 0; mt < 4; mt++)
                asm volatile(
                    "ldmatrix.sync.aligned.m8n8.x4.shared.b16 {%0,%1,%2,%3}, [%4];"
                    : "=r"(af[mt][0]), "=r"(af[mt][1]),
                      "=r"(af[mt][2]), "=r"(af[mt][3])
                    : "r"((aS + mt * 1024) ^ kx));
            uint32_t bf[4][2];
#pragma unroll
            for (int ntp = 0; ntp < 2; ntp++) {
                uint32_t r0, r1, r2, r3;
                asm volatile(
                    "ldmatrix.sync.aligned.m8n8.x4.shared.b16 {%0,%1,%2,%3}, [%4];"
                    : "=r"(r0), "=r"(r1), "=r"(r2), "=r"(r3)
                    : "r"((bS + ntp * 1024) ^ kx));
                bf[2*ntp][0]   = r0; bf[2*ntp][1]   = r2;
                bf[2*ntp+1][0] = r1; bf[2*ntp+1][1] = r3;
            }
#pragma unroll
            for (int mt = 0; mt < 4; mt++)
#pragma unroll
                for (int nt = 0; nt < 4; nt++)
                    asm volatile(
                        "mma.sync.aligned.m16n8k16.row.col.f32.f16.f16.f32 "
                        "{%0,%1,%2,%3}, {%4,%5,%6,%7}, {%8,%9}, {%0,%1,%2,%3};"
                        : "+f"(acc[mt][nt][0]), "+f"(acc[mt][nt][1]),
                          "+f"(acc[mt][nt][2]), "+f"(acc[mt][nt][3])
                        : "r"(af[mt][0]), "r"(af[mt][1]),
                          "r"(af[mt][2]), "r"(af[mt][3]),
                          "r"(bf[nt][0]), "r"(bf[nt][1]));
        }
    }

    // epilogue: bias + gelu -> f16
#pragma unroll
    for (int mt = 0; mt < 4; mt++) {
#pragma unroll
        for (int nt = 0; nt < 4; nt++) {
            const int row = row0 + warp_m + mt * 16 + g;
            const int col = col0 + warp_n + nt * 8 + tig * 2;
            const float b0 = bias[col], b1 = bias[col + 1];
#pragma unroll
            for (int h = 0; h < 2; h++) {
                const float v0 = acc[mt][nt][2*h]   + b0;
                const float v1 = acc[mt][nt][2*h+1] + b1;
                const float g0 = v0 * 0.5f * (1.0f + erff(v0 * 0.70710678f));
                const float g1 = v1 * 0.5f * (1.0f + erff(v1 * 0.70710678f));
                *(__half2*)(g_h16 + (size_t)(row + h * 8) * HID + col) =
                    __floats2half2_rn(g0, g1);
            }
        }
    }
}

// ---------------------------------------------------------------------------
// kLN: LayerNorm rows of g_h16, then angles = sigmoid(h @ entw + entb)*2pi
// ---------------------------------------------------------------------------
__global__ __launch_bounds__(256)
void kLN(const float* __restrict__ lnw,
         const float* __restrict__ lnb,
         const float* __restrict__ entw,
         const float* __restrict__ entb) {
    __shared__ float sh[8 * HID];
    const int row0 = blockIdx.x * 8;
    const int tid  = threadIdx.x;

    for (int i = tid; i < 4 * HID; i += 256) {
        const __half2 v = *((const __half2*)g_h16 + (size_t)row0 * (HID/2) + i);
        const float2 f = __half22float2(v);
        sh[2*i] = f.x; sh[2*i+1] = f.y;
    }
    __syncthreads();

    const int w = tid >> 5, lane = tid & 31;
    {
        float s = 0.f, s2 = 0.f;
        for (int k = lane; k < HID; k += 32) {
            const float v = sh[w * HID + k];
            s += v; s2 += v * v;
        }
#pragma unroll
        for (int o = 16; o; o >>= 1) {
            s  += __shfl_xor_sync(0xffffffffu, s,  o);
            s2 += __shfl_xor_sync(0xffffffffu, s2, o);
        }
        const float mean = s * (1.0f / HID);
        const float var  = s2 * (1.0f / HID) - mean * mean;
        const float inv  = rsqrtf(var + 1e-12f);
        for (int k = lane; k < HID; k += 32) {
            const float v = (sh[w * HID + k] - mean) * inv;
            sh[w * HID + k] = lnw[k] * v + lnb[k];
        }
    }

    for (int o = 0; o < NANG; o++) {
        float a = 0.f;
        for (int k = lane; k < HID; k += 32)
            a = fmaf(sh[w * HID + k], entw[k * NANG + o], a);
#pragma unroll
        for (int off = 16; off; off >>= 1)
            a += __shfl_xor_sync(0xffffffffu, a, off);
        if (lane == 0) {
            const float z  = a + entb[o];
            const float sg = 1.0f / (1.0f + expf(-z));
            g_ang[(row0 + w) * NANG + o] = sg * 6.283185307179586f;
        }
    }
}

// ---------------------------------------------------------------------------
// K2: quantum circuit. One block per row, 512 threads, statevector in shared.
// ---------------------------------------------------------------------------
__global__ __launch_bounds__(512)
void k2_quantum() {
    __shared__ float2 st[QDIM];
    __shared__ float cb[NANG], sb[NANG];
    const int row = blockIdx.x;
    const int tid = threadIdx.x;

    if (tid < NANG) {
        const float th = g_ang[row * NANG + tid] * 0.5f;
        sincosf(th, &sb[tid], &cb[tid]);
    }
    st[tid]       = (tid == 0) ? make_float2(1.f, 0.f) : make_float2(0.f, 0.f);
    st[tid + 512] = make_float2(0.f, 0.f);
    __syncthreads();

    for (int l = 0; l < 2; l++) {
#pragma unroll
        for (int q = 0; q < 10; q++) {
            const int b = 9 - q;
            const int S = 1 << b;
            const float c = cb[l * 10 + q];
            const float s = sb[l * 10 + q];
            const int low = tid & (S - 1);
            const int i0  = ((tid >> b) << (b + 1)) | low;
            const int i1  = i0 | S;
            const float2 a0 = st[i0];
            const float2 a1 = st[i1];
            float2 b0, b1;
            b0.x = c * a0.x + s * a1.y;
            b0.y = c * a0.y - s * a1.x;
            b1.x = c * a1.x + s * a0.y;
            b1.y = c * a1.y - s * a0.x;
            st[i0] = b0;
            st[i1] = b1;
            __syncthreads();
        }
        int j0 = tid, j1 = tid + 512;
#pragma unroll
        for (int q = 9; q >= 0; q--) {
            const int cbit = 9 - q;
            const int tbit = 9 - ((q + 1) % 10);
            j0 ^= ((j0 >> cbit) & 1) << tbit;
            j1 ^= ((j1 >> cbit) & 1) << tbit;
        }
        const float2 r0 = st[j0];
        const float2 r1 = st[j1];
        __syncthreads();
        st[tid]       = r0;
        st[tid + 512] = r1;
        __syncthreads();
    }

    const float2 v0 = st[tid];
    const float2 v1 = st[tid + 512];
    g_probs16[row * QDIM + tid]       = __float2half_rn(v0.x * v0.x + v0.y * v0.y);
    g_probs16[row * QDIM + tid + 512] = __float2half_rn(v1.x * v1.x + v1.y * v1.y);
}

// ---------------------------------------------------------------------------
// K3 v5: out = probs @ g_wt^T + proj_b  (f16 x f16 -> f32)
// CTA 128x128xBK64, 3-stage cp.async (96 KB, 2 CTAs/SM), 16 barrier epochs,
// 4 MMA k-groups per epoch. One 128B smem line per row; addr ^ (ks<<5).
// ---------------------------------------------------------------------------
#define K3_BK      64
#define K3_STAGES  3
#define K3_A_STG   16384      // 128 rows * 128 B
#define K3_B_STG   16384
#define K3_B_BASE  (K3_STAGES * K3_A_STG)
#define K3_SMEM    (K3_STAGES * (K3_A_STG + K3_B_STG))   // 96 KB

__global__ __launch_bounds__(256, 2)
void k3_proj_f16v5(const float* __restrict__ pb,
                   float* __restrict__ out) {
    extern __shared__ char smem[];
    const uint32_t sA = smem_u32(smem);
    const uint32_t sB = sA + K3_B_BASE;

    const int tid  = threadIdx.x;
    const int w    = tid >> 5;
    const int lane = tid & 31;
    const int g    = lane >> 2;
    const int tig  = lane & 3;

    const int row0 = blockIdx.x * 128;
    const int col0 = blockIdx.y * 128;
    const int warp_m = (w & 1) * 64;
    const int warp_n = (w >> 1) * 32;

    const __half* Agbase = g_probs16 + (size_t)row0 * QDIM;
    const __half* Bgbase = g_wt      + (size_t)col0 * QDIM;

    // consumer ldmatrix base (ks=0); per-ks address = base ^ (ks<<5)
    const int l16 = lane & 15;
    const int khf = lane >> 4;
    const uint32_t aLM = sA + swz64(warp_m + l16, khf);
    const uint32_t bLM = sB + swz64(warp_n + l16, khf);

    float acc[4][4][4];
#pragma unroll
    for (int i = 0; i < 4; i++)
#pragma unroll
        for (int j = 0; j < 4; j++)
#pragma unroll
            for (int c = 0; c < 4; c++) acc[i][j][c] = 0.f;

    const int KB = QDIM / K3_BK;   // 16

    // prologue: fill stages 0,1. 1024 chunks per tile, 4 per thread.
#pragma unroll
    for (int s = 0; s < K3_STAGES - 1; s++) {
        const int k0 = s * K3_BK;
#pragma unroll
        for (int j = 0; j < 4; j++) {
            const int i = tid + j * 256;
            const int r = i >> 3, kc = i & 7;
            cp16(sA + s * K3_A_STG + swz64(r, kc),
                 Agbase + (size_t)r * QDIM + k0 + kc * 8);
            cp16(sB + s * K3_B_STG + swz64(r, kc),
                 Bgbase + (size_t)r * QDIM + k0 + kc * 8);
        }
        asm volatile("cp.async.commit_group;");
    }

    int s_cur = 0, s_nxt = K3_STAGES - 1;
    for (int kb = 0; kb < KB; kb++) {
        asm volatile("cp.async.wait_group %0;" :: "n"(K3_STAGES - 2));
        __syncthreads();

        {
            const int kn = kb + K3_STAGES - 1;
            if (kn < KB) {
                const int k0 = kn * K3_BK;
#pragma unroll
                for (int j = 0; j < 4; j++) {
                    const int i = tid + j * 256;
                    const int r = i >> 3, kc = i & 7;
                    cp16(sA + s_nxt * K3_A_STG + swz64(r, kc),
                         Agbase + (size_t)r * QDIM + k0 + kc * 8);
                    cp16(sB + s_nxt * K3_B_STG + swz64(r, kc),
                         Bgbase + (size_t)r * QDIM + k0 + kc * 8);
                }
            }
            asm volatile("cp.async.commit_group;");
        }

        const uint32_t aS = aLM + s_cur * K3_A_STG;
        const uint32_t bS = bLM + s_cur * K3_B_STG;
#pragma unroll
        for (int ks = 0; ks < 4; ks++) {
            const uint32_t kx = (uint32_t)ks << 5;
            uint32_t af[4][4];
#pragma unroll
            for (int mt = 0; mt < 4; mt++) {
                asm volatile(
                    "ldmatrix.sync.aligned.m8n8.x4.shared.b16 {%0,%1,%2,%3}, [%4];"
                    : "=r"(af[mt][0]), "=r"(af[mt][1]),
                      "=r"(af[mt][2]), "=r"(af[mt][3])
                    : "r"((aS + mt * 2048) ^ kx));
            }
            uint32_t bf[4][2];
#pragma unroll
            for (int ntp = 0; ntp < 2; ntp++) {
                uint32_t r0, r1, r2, r3;
                asm volatile(
                    "ldmatrix.sync.aligned.m8n8.x4.shared.b16 {%0,%1,%2,%3}, [%4];"
                    : "=r"(r0), "=r"(r1), "=r"(r2), "=r"(r3)
                    : "r"((bS + ntp * 2048) ^ kx));
                bf[2*ntp][0]   = r0; bf[2*ntp][1]   = r2;
                bf[2*ntp+1][0] = r1; bf[2*ntp+1][1] = r3;
            }
#pragma unroll
            for (int mt = 0; mt < 4; mt++)
#pragma unroll
                for (int nt = 0; nt < 4; nt++) {
                    asm volatile(
                        "mma.sync.aligned.m16n8k16.row.col.f32.f16.f16.f32 "
                        "{%0,%1,%2,%3}, {%4,%5,%6,%7}, {%8,%9}, {%0,%1,%2,%3};"
                        : "+f"(acc[mt][nt][0]), "+f"(acc[mt][nt][1]),
                          "+f"(acc[mt][nt][2]), "+f"(acc[mt][nt][3])
                        : "r"(af[mt][0]), "r"(af[mt][1]),
                          "r"(af[mt][2]), "r"(af[mt][3]),
                          "r"(bf[nt][0]), "r"(bf[nt][1]));
                }
        }

        s_cur = (s_cur + 1 < K3_STAGES) ? s_cur + 1 : 0;
        s_nxt = (s_nxt + 1 < K3_STAGES) ? s_nxt + 1 : 0;
    }

    // epilogue
#pragma unroll
    for (int mt = 0; mt < 4; mt++) {
#pragma unroll
        for (int nt = 0; nt < 4; nt++) {
            const int row = row0 + warp_m + mt * 16 + g;
            const int col = col0 + warp_n + nt * 8 + tig * 2;
            if (col < VOCAB) {   // VOCAB even -> pair never straddles
                const float b0 = pb[col], b1 = pb[col + 1];
                float2 v0 = make_float2(acc[mt][nt][0] + b0, acc[mt][nt][1] + b1);
                float2 v1 = make_float2(acc[mt][nt][2] + b0, acc[mt][nt][3] + b1);
                __stcs((float2*)(out + (size_t)row * VOCAB + col), v0);
                __stcs((float2*)(out + (size_t)(row + 8) * VOCAB + col), v1);
            }
        }
    }
}

// ---------------------------------------------------------------------------
extern "C" void kernel_launch(void* const* d_in, const int* in_sizes, int n_in,
                              void* d_out, int out_size) {
    const float* x    = (const float*)d_in[0];
    const float* W    = (const float*)d_in[1];
    const float* db   = (const float*)d_in[2];
    const float* lnw  = (const float*)d_in[3];
    const float* lnb  = (const float*)d_in[4];
    const float* entw = (const float*)d_in[5];
    const float* entb = (const float*)d_in[6];
    const float* pw   = (const float*)d_in[7];
    const float* pb   = (const float*)d_in[8];
    float* out = (float*)d_out;

    kCvtX<<<M_ROWS * HID / 1024, 256>>>(x);
    dim3 gT1(HID / 32, HID / 32);
    kT1_transpose<<<gT1, 256>>>(W);
    dim3 gT(VPAD / 32, QDIM / 32);
    kT_transpose<<<gT, 256>>>(pw);

    cudaFuncSetAttribute(k1_gemm,
                         cudaFuncAttributeMaxDynamicSharedMemorySize, GEMM_SMEM);
    dim3 g1(M_ROWS / 128, HID / 128);      // (32, 6)
    k1_gemm<<<g1, 256, GEMM_SMEM>>>(db);

    kLN<<<M_ROWS / 8, 256>>>(lnw, lnb, entw, entb);
    k2_quantum<<<M_ROWS, 512>>>();

    cudaFuncSetAttribute(k3_proj_f16v5,
                         cudaFuncAttributeMaxDynamicSharedMemorySize, K3_SMEM);
    dim3 g3(M_ROWS / 128, VPAD / 128);     // (32, 239)
    k3_proj_f16v5<<<g3, 256, K3_SMEM>>>(pb, out);
}